// round 6
// baseline (speedup 1.0000x reference)
#include <cuda_runtime.h>

// MPS forward v3: packed f32x2 FMA + pair-per-lane layout.
// y_{n+1}[b] = act( sum_{a,i} y_n[a] * A[c,site,a,i,b] * x[batch,i,site] )
// BATCH=1024, CHANNEL=10, LENGTH=784, CHI=64, D=2.
//
// One WARP = one chain of (channel, 8 batches); 1280 single-warp blocks
// (8.65/SM, 4% tail imbalance). Lane l owns column PAIR (2l, 2l+1) for BOTH
// i-halves -> no cross-lane reduction. A read via two LDG.64 per a-row
// (coalesced, L2-cached). y kept in smem DUPLICATED (y[a] at 2a,2a+1) so one
// broadcast LDS.128 yields two ready-packed (ya,ya) f32x2 multipliers.
// Inner product uses fma.rn.f32x2: 2 fp32 FMA per issued instruction.

namespace {
constexpr int LEN    = 784;
constexpr int NCH    = 10;
constexpr int BTCH   = 1024;
constexpr int TB     = 8;            // batches per warp
constexpr int SITE_F = 8192;         // floats per (channel,site) tensor
}

typedef unsigned long long ull;

__device__ float g_xT[2 * LEN * BTCH];   // x transposed: [i][site][batch]

__global__ void xpose_kernel(const float* __restrict__ x)
{
    int idx = blockIdx.x * blockDim.x + threadIdx.x;
    if (idx >= 2 * LEN * BTCH) return;
    int b    = idx & (BTCH - 1);
    int t    = idx >> 10;            // i*LEN + site
    int i    = t / LEN;
    int site = t - i * LEN;
    g_xT[idx] = x[(size_t)b * (2 * LEN) + i * LEN + site];
}

__device__ __forceinline__ float act_sig(float v) {
    // (tanh(v)+1)/2 == sigmoid(2v)
    return __fdividef(1.0f, 1.0f + __expf(-2.0f * v));
}

__device__ __forceinline__ ull ffma2(ull a, ull b, ull c) {
    ull d;
    asm("fma.rn.f32x2 %0, %1, %2, %3;" : "=l"(d) : "l"(a), "l"(b), "l"(c));
    return d;
}

__device__ __forceinline__ ull packdup(float v) {
    ull r; unsigned u = __float_as_uint(v);
    asm("mov.b64 %0, {%1, %2};" : "=l"(r) : "r"(u), "r"(u));
    return r;
}

__device__ __forceinline__ float2 unpk(ull v) {
    unsigned lo, hi;
    asm("mov.b64 {%0, %1}, %2;" : "=r"(lo), "=r"(hi) : "l"(v));
    return make_float2(__uint_as_float(lo), __uint_as_float(hi));
}

__device__ __forceinline__ ull ldgu64(const float* p) {
    return __ldg(reinterpret_cast<const ull*>(p));
}

__global__ void __launch_bounds__(32)
mps_main(const float* __restrict__ tens, float* __restrict__ out)
{
    __shared__ float ys[2][TB][128];   // dup'd carried state: y[a] at 2a,2a+1

    const int lane = threadIdx.x;
    const int wid  = blockIdx.x;
    const int c    = wid % NCH;
    const int bb   = (wid / NCH) * TB;

    // init y (input of site 0): y[a] = (a==0) -> dup positions 0,1 are 1.0
    for (int k = lane; k < TB * 128; k += 32)
        (&ys[0][0][0])[k] = ((k & 127) < 2) ? 1.0f : 0.0f;
    __syncwarp();

    // lane's pair base: i0 at a*128 + 2*lane, i1 at +64
    const float* T0 = tens + (size_t)c * LEN * SITE_F + 2 * lane;

    // A double buffer: [parity][i][j], 4 a-rows per phase
    ull Ab[2][2][4];
    #pragma unroll
    for (int j = 0; j < 4; ++j) {
        Ab[0][0][j] = ldgu64(T0 + j * 128);
        Ab[0][1][j] = ldgu64(T0 + j * 128 + 64);
    }

    int p = 0;
    for (int site = 0; site < LEN; ++site) {
        const float* Ts = T0 + (size_t)site * SITE_F;

        // x staging: lane<16 holds x[i=lane>>3][site][bb + (lane&7)]
        float xl = 0.f;
        if (lane < 16)
            xl = g_xT[(lane >> 3) * (LEN * BTCH) + site * BTCH + bb + (lane & 7)];

        ull acc0[TB], acc1[TB];
        #pragma unroll
        for (int bt = 0; bt < TB; ++bt) { acc0[bt] = 0ull; acc1[bt] = 0ull; }

        const float* yrow = &ys[p][0][0];

        #pragma unroll 2
        for (int ph = 0; ph < 16; ++ph) {
            const int cur = ph & 1;
            const int nxt = cur ^ 1;
            // prefetch phase ph+1 (or next site's phase 0)
            {
                const float* rp;
                if (ph < 15)              rp = Ts + (4 * (ph + 1)) * 128;
                else if (site < LEN - 1)  rp = Ts + SITE_F;          // next site ph0
                else                      rp = Ts;                    // dummy
                #pragma unroll
                for (int j = 0; j < 4; ++j) {
                    Ab[nxt][0][j] = ldgu64(rp + j * 128);
                    Ab[nxt][1][j] = ldgu64(rp + j * 128 + 64);
                }
            }
            // consume phase ph: a-values 4ph..4ph+3, dup'd at floats 8ph..8ph+7
            #pragma unroll
            for (int bt = 0; bt < TB; ++bt) {
                const ulonglong2* yq =
                    reinterpret_cast<const ulonglong2*>(yrow + bt * 128 + 8 * ph);
                const ulonglong2 ya = yq[0];
                const ulonglong2 yb = yq[1];
                acc0[bt] = ffma2(ya.x, Ab[cur][0][0], acc0[bt]);
                acc1[bt] = ffma2(ya.x, Ab[cur][1][0], acc1[bt]);
                acc0[bt] = ffma2(ya.y, Ab[cur][0][1], acc0[bt]);
                acc1[bt] = ffma2(ya.y, Ab[cur][1][1], acc1[bt]);
                acc0[bt] = ffma2(yb.x, Ab[cur][0][2], acc0[bt]);
                acc1[bt] = ffma2(yb.x, Ab[cur][1][2], acc1[bt]);
                acc0[bt] = ffma2(yb.y, Ab[cur][0][3], acc0[bt]);
                acc1[bt] = ffma2(yb.y, Ab[cur][1][3], acc1[bt]);
            }
        }

        if (site == LEN - 1) {
            // last site: no activation; only column 0 survives (lane 0 pair.x)
            #pragma unroll
            for (int bt = 0; bt < TB; ++bt) {
                const float xv0 = __shfl_sync(0xffffffffu, xl, bt);
                const float xv1 = __shfl_sync(0xffffffffu, xl, 8 + bt);
                const float2 f0 = unpk(acc0[bt]);
                const float2 f1 = unpk(acc1[bt]);
                if (lane == 0)
                    out[(size_t)(bb + bt) * NCH + c] = fmaf(xv0, f0.x, xv1 * f1.x);
            }
        } else {
            // bond dimension of this site's output
            const int nn = site + 1;
            const int up = (nn >= 6) ? 64 : (1 << nn);
            const int dn = ((LEN - nn) >= 6) ? 64 : (1 << (LEN - nn));
            const int dnext = (up < dn) ? up : dn;
            const int c0 = 2 * lane;

            #pragma unroll
            for (int bt = 0; bt < TB; ++bt) {
                const float xv0 = __shfl_sync(0xffffffffu, xl, bt);
                const float xv1 = __shfl_sync(0xffffffffu, xl, 8 + bt);
                const ull v = ffma2(packdup(xv0), acc0[bt],
                                    ffma2(packdup(xv1), acc1[bt], 0ull));
                const float2 f = unpk(v);
                const float o0 = (c0 + 0 < dnext) ? act_sig(f.x) : 0.f;
                const float o1 = (c0 + 1 < dnext) ? act_sig(f.y) : 0.f;
                // dup store: cols (2l,2l+1) -> floats [4l..4l+3]
                *reinterpret_cast<float4*>(&ys[1 - p][bt][4 * lane]) =
                    make_float4(o0, o0, o1, o1);
            }
            __syncwarp();
            p ^= 1;
        }
    }
}

extern "C" void kernel_launch(void* const* d_in, const int* in_sizes, int n_in,
                              void* d_out, int out_size)
{
    const float* a0 = (const float*)d_in[0];
    const float* a1 = (const float*)d_in[1];
    // x: 1024*2*784 = 1,605,632 ; tensors: 10*784*64*2*64 = 64,225,280
    const float* x = a0;
    const float* t = a1;
    if (n_in >= 2 && in_sizes[0] > in_sizes[1]) { x = a1; t = a0; }

    const int nx = 2 * LEN * BTCH;
    xpose_kernel<<<(nx + 255) / 256, 256>>>(x);

    const int blocks = NCH * (BTCH / TB);   // 10 * 128 = 1280 single-warp blocks
    mps_main<<<blocks, 32>>>(t, (float*)d_out);
}

// round 7
// speedup vs baseline: 1.2536x; 1.2536x over previous
#include <cuda_runtime.h>

// MPS forward v4: quad-per-lane + fma.rn.f32x2 + 4.3 warps/SMSP.
// y_{n+1}[b] = act( sum_{a,i} y_n[a] * A[c,site,a,i,b] * x[batch,i,site] )
// BATCH=1024, CHANNEL=10, LENGTH=784, CHI=64, D=2.
//
// One WARP = one chain (channel, 4 batches); 2560 single-warp blocks
// (17.3 warps/SM -> 4.3/SMSP, the occupancy point R5 proved out).
// Lane l: i-half = l>>4, columns 4*(l&15)..+3. One LDG.128 per a-row per
// lane covers the full 512B row warp-wide (L1-cached across warps).
// y carried in smem DUPLICATED (y[a] at 2a,2a+1): one broadcast LDS.128
// yields two ready-packed (ya,ya) f32x2 multipliers. Inner product uses
// fma.rn.f32x2 -> 2 fp32 FMA per issue slot.

namespace {
constexpr int LEN    = 784;
constexpr int NCH    = 10;
constexpr int BTCH   = 1024;
constexpr int TB     = 4;            // batches per warp
constexpr int SITE_F = 8192;         // floats per (channel,site) tensor
}

typedef unsigned long long ull;

__device__ float g_xT[2 * LEN * BTCH];   // x transposed: [i][site][batch]

__global__ void xpose_kernel(const float* __restrict__ x)
{
    int idx = blockIdx.x * blockDim.x + threadIdx.x;
    if (idx >= 2 * LEN * BTCH) return;
    int b    = idx & (BTCH - 1);
    int t    = idx >> 10;            // i*LEN + site
    int i    = t / LEN;
    int site = t - i * LEN;
    g_xT[idx] = x[(size_t)b * (2 * LEN) + i * LEN + site];
}

__device__ __forceinline__ float act_sig(float v) {
    // (tanh(v)+1)/2 == sigmoid(2v)
    return __fdividef(1.0f, 1.0f + __expf(-2.0f * v));
}

__device__ __forceinline__ ull ffma2(ull a, ull b, ull c) {
    ull d;
    asm("fma.rn.f32x2 %0, %1, %2, %3;" : "=l"(d) : "l"(a), "l"(b), "l"(c));
    return d;
}

__device__ __forceinline__ ull packdup(float v) {
    ull r; unsigned u = __float_as_uint(v);
    asm("mov.b64 %0, {%1, %2};" : "=l"(r) : "r"(u), "r"(u));
    return r;
}

__device__ __forceinline__ float2 unpk(ull v) {
    unsigned lo, hi;
    asm("mov.b64 {%0, %1}, %2;" : "=r"(lo), "=r"(hi) : "l"(v));
    return make_float2(__uint_as_float(lo), __uint_as_float(hi));
}

__device__ __forceinline__ ulonglong2 ldg128(const float* p) {
    return __ldg(reinterpret_cast<const ulonglong2*>(p));
}

__global__ void __launch_bounds__(32)
mps_main(const float* __restrict__ tens, float* __restrict__ out)
{
    __shared__ float ys[2][TB][128];   // dup'd carried state: y[a] at 2a,2a+1

    const int lane = threadIdx.x;
    const int wid  = blockIdx.x;
    const int c    = wid % NCH;
    const int bb   = (wid / NCH) * TB;
    const int li   = lane & 15;        // column quad index (cols 4li..4li+3)
    const int ih   = lane >> 4;        // i-half

    // init y (input of site 0): y[a] = (a==0) -> dup floats 0,1 are 1.0
    #pragma unroll
    for (int k = lane; k < TB * 128; k += 32)
        (&ys[0][0][0])[k] = ((k & 127) < 2) ? 1.0f : 0.0f;
    __syncwarp();

    // lane's quad base within each 128-float a-row
    const float* T0 = tens + (size_t)c * LEN * SITE_F + ih * 64 + 4 * li;

    // A double buffer: 4 a-rows per phase, each row = one ulonglong2 (q01,q23)
    ulonglong2 Ab[2][4];
    #pragma unroll
    for (int j = 0; j < 4; ++j)
        Ab[0][j] = ldg128(T0 + j * 128);   // site 0, rows 0..3

    int p = 0;
    for (int site = 0; site < LEN; ++site) {
        const float* Ts = T0 + (size_t)site * SITE_F;

        // x staging: lane<8 holds x[i=lane>>2][site][bb + (lane&3)]
        float xl = 0.f;
        if (lane < 8)
            xl = g_xT[(lane >> 2) * (LEN * BTCH) + site * BTCH + bb + (lane & 3)];

        ull a01[TB], a23[TB];
        #pragma unroll
        for (int bt = 0; bt < TB; ++bt) { a01[bt] = 0ull; a23[bt] = 0ull; }

        const float* yrow = &ys[p][0][0];

        #pragma unroll 4
        for (int ph = 0; ph < 16; ++ph) {
            const int cur = ph & 1;
            const int nxt = cur ^ 1;
            // prefetch phase ph+1 (or next site's phase 0)
            {
                const float* rp;
                if (ph < 15)              rp = Ts + 4 * (ph + 1) * 128;
                else if (site < LEN - 1)  rp = Ts + SITE_F;
                else                      rp = Ts;           // dummy
                #pragma unroll
                for (int j = 0; j < 4; ++j)
                    Ab[nxt][j] = ldg128(rp + j * 128);
            }
            // consume phase ph: a = 4ph..4ph+3, dup'd at floats 8ph..8ph+7
            #pragma unroll
            for (int bt = 0; bt < TB; ++bt) {
                const ulonglong2* yq =
                    reinterpret_cast<const ulonglong2*>(yrow + bt * 128 + 8 * ph);
                const ulonglong2 ya = yq[0];   // (y[4ph],y[4ph])   (y[4ph+1],..)
                const ulonglong2 yb = yq[1];
                a01[bt] = ffma2(ya.x, Ab[cur][0].x, a01[bt]);
                a23[bt] = ffma2(ya.x, Ab[cur][0].y, a23[bt]);
                a01[bt] = ffma2(ya.y, Ab[cur][1].x, a01[bt]);
                a23[bt] = ffma2(ya.y, Ab[cur][1].y, a23[bt]);
                a01[bt] = ffma2(yb.x, Ab[cur][2].x, a01[bt]);
                a23[bt] = ffma2(yb.x, Ab[cur][2].y, a23[bt]);
                a01[bt] = ffma2(yb.y, Ab[cur][3].x, a01[bt]);
                a23[bt] = ffma2(yb.y, Ab[cur][3].y, a23[bt]);
            }
        }

        if (site == LEN - 1) {
            // last site: no activation; only column 0 survives (lane0, i0)
            #pragma unroll
            for (int bt = 0; bt < TB; ++bt) {
                const ull z01 = __shfl_xor_sync(0xffffffffu, a01[bt], 16);
                const float xv0 = __shfl_sync(0xffffffffu, xl, bt);
                const float xv1 = __shfl_sync(0xffffffffu, xl, 4 + bt);
                if (lane == 0) {
                    const float f0 = unpk(a01[bt]).x;   // i0 col0
                    const float f1 = unpk(z01).x;       // i1 col0
                    out[(size_t)(bb + bt) * NCH + c] = fmaf(xv0, f0, xv1 * f1);
                }
            }
        } else {
            // bond dimension of this site's output
            const int nn = site + 1;
            const int up = (nn >= 6) ? 64 : (1 << nn);
            const int dn = ((LEN - nn) >= 6) ? 64 : (1 << (LEN - nn));
            const int dnext = (up < dn) ? up : dn;
            const int cb = 4 * li;

            #pragma unroll
            for (int bt = 0; bt < TB; ++bt) {
                const ull z01 = __shfl_xor_sync(0xffffffffu, a01[bt], 16);
                const ull z23 = __shfl_xor_sync(0xffffffffu, a23[bt], 16);
                const float xv0 = __shfl_sync(0xffffffffu, xl, bt);
                const float xv1 = __shfl_sync(0xffffffffu, xl, 4 + bt);
                if (ih == 0) {
                    const ull px0 = packdup(xv0);
                    const ull px1 = packdup(xv1);
                    const ull v01 = ffma2(px0, a01[bt], ffma2(px1, z01, 0ull));
                    const ull v23 = ffma2(px0, a23[bt], ffma2(px1, z23, 0ull));
                    const float2 f01 = unpk(v01);
                    const float2 f23 = unpk(v23);
                    const float o0 = (cb + 0 < dnext) ? act_sig(f01.x) : 0.f;
                    const float o1 = (cb + 1 < dnext) ? act_sig(f01.y) : 0.f;
                    const float o2 = (cb + 2 < dnext) ? act_sig(f23.x) : 0.f;
                    const float o3 = (cb + 3 < dnext) ? act_sig(f23.y) : 0.f;
                    // dup store: cols 4li..4li+3 -> floats 8li..8li+7
                    float* yw = &ys[1 - p][bt][8 * li];
                    *reinterpret_cast<float4*>(yw)     = make_float4(o0, o0, o1, o1);
                    *reinterpret_cast<float4*>(yw + 4) = make_float4(o2, o2, o3, o3);
                }
            }
            __syncwarp();
            p ^= 1;
        }
    }
}

extern "C" void kernel_launch(void* const* d_in, const int* in_sizes, int n_in,
                              void* d_out, int out_size)
{
    const float* a0 = (const float*)d_in[0];
    const float* a1 = (const float*)d_in[1];
    // x: 1024*2*784 = 1,605,632 ; tensors: 10*784*64*2*64 = 64,225,280
    const float* x = a0;
    const float* t = a1;
    if (n_in >= 2 && in_sizes[0] > in_sizes[1]) { x = a1; t = a0; }

    const int nx = 2 * LEN * BTCH;
    xpose_kernel<<<(nx + 255) / 256, 256>>>(x);

    const int blocks = NCH * (BTCH / TB);   // 10 * 256 = 2560 single-warp blocks
    mps_main<<<blocks, 32>>>(t, (float*)d_out);
}